// round 7
// baseline (speedup 1.0000x reference)
#include <cuda_runtime.h>
#include <cuda_bf16.h>
#include <cstdint>
#include <cstddef>

#define H 2048
#define NACT 64
#define STEPS 32
#define NLAYERS 2
#define JPB 4   // j-values per cell block

// ---------------- device state ----------------
__device__ __align__(16) float g_h[2][NLAYERS][H];   // [parity][layer]
__device__ __align__(16) float g_c[NLAYERS][H];
__device__ __align__(16) float g_x[H];
__device__ __align__(16) float g_part[2][NACT];      // head partial dots
__device__ float g_logp_sum;
__device__ int   g_action;
__device__ int   g_done;

// bf16 weight scratch: [layer][which][row][permuted 2048 elems]
// Within each row, uint4 group (it*32+l) holds src float4s (64*it+l) and (64*it+32+l).
__device__ __align__(16) __nv_bfloat16 g_wbf[(size_t)NLAYERS * 2 * 4 * H * H];

// ---------------- threefry2x32-20 (bit-exact JAX core) ----------------
__device__ __forceinline__ uint32_t rotl32(uint32_t v, int d) {
    return (v << d) | (v >> (32 - d));
}

__device__ __forceinline__ void threefry2x32(uint32_t k0, uint32_t k1,
                                             uint32_t x0, uint32_t x1,
                                             uint32_t& o0, uint32_t& o1) {
    const uint32_t ks2 = k0 ^ k1 ^ 0x1BD11BDAu;
    x0 += k0; x1 += k1;
    x0 += x1; x1 = rotl32(x1, 13); x1 ^= x0;
    x0 += x1; x1 = rotl32(x1, 15); x1 ^= x0;
    x0 += x1; x1 = rotl32(x1, 26); x1 ^= x0;
    x0 += x1; x1 = rotl32(x1, 6);  x1 ^= x0;
    x0 += k1; x1 += ks2 + 1u;
    x0 += x1; x1 = rotl32(x1, 17); x1 ^= x0;
    x0 += x1; x1 = rotl32(x1, 29); x1 ^= x0;
    x0 += x1; x1 = rotl32(x1, 16); x1 ^= x0;
    x0 += x1; x1 = rotl32(x1, 24); x1 ^= x0;
    x0 += ks2; x1 += k0 + 2u;
    x0 += x1; x1 = rotl32(x1, 13); x1 ^= x0;
    x0 += x1; x1 = rotl32(x1, 15); x1 ^= x0;
    x0 += x1; x1 = rotl32(x1, 26); x1 ^= x0;
    x0 += x1; x1 = rotl32(x1, 6);  x1 ^= x0;
    x0 += k0; x1 += k1 + 3u;
    x0 += x1; x1 = rotl32(x1, 17); x1 ^= x0;
    x0 += x1; x1 = rotl32(x1, 29); x1 ^= x0;
    x0 += x1; x1 = rotl32(x1, 16); x1 ^= x0;
    x0 += x1; x1 = rotl32(x1, 24); x1 ^= x0;
    x0 += k1; x1 += ks2 + 4u;
    x0 += x1; x1 = rotl32(x1, 13); x1 ^= x0;
    x0 += x1; x1 = rotl32(x1, 15); x1 ^= x0;
    x0 += x1; x1 = rotl32(x1, 26); x1 ^= x0;
    x0 += x1; x1 = rotl32(x1, 6);  x1 ^= x0;
    x0 += ks2; x1 += k0 + 5u;
    o0 = x0; o1 = x1;
}

__device__ __forceinline__ float jax_uniform(uint32_t bits) {
    const float tiny = 1.1754943508222875e-38f;
    uint32_t fb = (bits >> 9) | 0x3f800000u;
    float u = __uint_as_float(fb) - 1.0f;
    u = u * 1.0f + tiny;
    return fmaxf(tiny, u);
}

// ---------------- weight conversion fp32 -> bf16 (permuted layout) ----------------
__global__ void convert_kernel(const float* __restrict__ w_ih,
                               const float* __restrict__ w_hh) {
    const size_t MAT  = (size_t)4 * H * H;
    const size_t NOUT = (size_t)NLAYERS * 2 * MAT / 8;
    size_t stride = (size_t)gridDim.x * blockDim.x;
    for (size_t o = (size_t)blockIdx.x * blockDim.x + threadIdx.x; o < NOUT; o += stride) {
        size_t rrow = o >> 8;
        int g  = (int)(o & 255);
        int it = g >> 5, l = g & 31;
        int mat = (int)(rrow >> 13);
        size_t rloc = rrow & 8191;
        int layer = mat >> 1, which = mat & 1;
        const float4* s4 = reinterpret_cast<const float4*>(
            (which ? w_hh : w_ih) + (size_t)layer * MAT + rloc * H);
        int p = 64 * it + l;
        float4 sp = s4[p];
        float4 sq = s4[p + 32];
        __nv_bfloat162 c0 = __floats2bfloat162_rn(sp.x, sp.y);
        __nv_bfloat162 c1 = __floats2bfloat162_rn(sp.z, sp.w);
        __nv_bfloat162 c2 = __floats2bfloat162_rn(sq.x, sq.y);
        __nv_bfloat162 c3 = __floats2bfloat162_rn(sq.z, sq.w);
        uint4 packed;
        packed.x = *reinterpret_cast<uint32_t*>(&c0);
        packed.y = *reinterpret_cast<uint32_t*>(&c1);
        packed.z = *reinterpret_cast<uint32_t*>(&c2);
        packed.w = *reinterpret_cast<uint32_t*>(&c3);
        reinterpret_cast<uint4*>(g_wbf)[o] = packed;
    }
}

// ---------------- init ----------------
__global__ void init_kernel(const float* __restrict__ start_token) {
    int i = blockIdx.x * blockDim.x + threadIdx.x;
    if (i < H) {
        g_x[i] = start_token[i];
        g_c[0][i] = 0.f; g_c[1][i] = 0.f;
        g_h[0][0][i] = 0.f; g_h[0][1][i] = 0.f;
        g_h[1][0][i] = 0.f; g_h[1][1][i] = 0.f;
        if (i == 0) { g_logp_sum = 0.f; g_action = 0; g_done = 0; }
    }
}

// ---------------- fused LSTM cell (pipelined, 4 j per block) ----------------
// grid = H/JPB blocks. 8 warps: warp w covers (gate=w&3, which=w>>2).
// Each warp streams JPB consecutive weight rows with a rolling register
// double-buffer so ~4KB/warp stays in flight throughout.
__global__ void __launch_bounds__(256, 2)
cell_kernel(const float* __restrict__ bih, const float* __restrict__ bhh,
            int layer, int t) {
    const int tid  = threadIdx.x;
    const int j0   = blockIdx.x * JPB;
    const int w    = tid >> 5;
    const int lane = tid & 31;
    const int gate = w & 3;
    const int which = w >> 2;
    const int par_in  = t & 1;
    const int par_out = (t + 1) & 1;

    const size_t MAT = (size_t)4 * H * H;
    const uint4* row4 = reinterpret_cast<const uint4*>(
        g_wbf + ((size_t)layer * 2 + which) * MAT + (size_t)(gate * H + j0) * H);
    const int ROWSTRIDE = H / 8;   // uint4 per row (256)

    // prefetch row 0
    uint4 bufA[8], bufB[8];
#pragma unroll
    for (int it = 0; it < 8; it++) bufA[it] = row4[it * 32 + lane];

    // stage both vectors into smem while first loads are in flight
    __shared__ float4 sv[2][512];
    {
        const float4* v0 = reinterpret_cast<const float4*>(
            (layer == 0) ? g_x : g_h[par_out][0]);
        const float4* v1 = reinterpret_cast<const float4*>(g_h[par_in][layer]);
        sv[0][tid]       = v0[tid];
        sv[0][tid + 256] = v0[tid + 256];
        sv[1][tid]       = v1[tid];
        sv[1][tid + 256] = v1[tid + 256];
    }
    __syncthreads();

    const float4* svv = sv[which];
    __shared__ float sm[JPB][8];

#define CELL_PREFETCH(BUF, JJ)                                               \
    {                                                                        \
        const uint4* rp = row4 + (JJ) * ROWSTRIDE;                           \
        _Pragma("unroll")                                                    \
        for (int it = 0; it < 8; it++) BUF[it] = rp[it * 32 + lane];         \
    }

#define CELL_COMPUTE(BUF, JJ)                                                \
    {                                                                        \
        float s0 = 0.f, s1 = 0.f, s2 = 0.f, s3 = 0.f;                        \
        _Pragma("unroll")                                                    \
        for (int it = 0; it < 8; it++) {                                     \
            float4 b0 = svv[64 * it + lane];                                 \
            float4 b1 = svv[64 * it + 32 + lane];                            \
            float2 f0 = __bfloat1622float2(*reinterpret_cast<__nv_bfloat162*>(&BUF[it].x)); \
            float2 f1 = __bfloat1622float2(*reinterpret_cast<__nv_bfloat162*>(&BUF[it].y)); \
            float2 f2 = __bfloat1622float2(*reinterpret_cast<__nv_bfloat162*>(&BUF[it].z)); \
            float2 f3 = __bfloat1622float2(*reinterpret_cast<__nv_bfloat162*>(&BUF[it].w)); \
            s0 = fmaf(f0.x, b0.x, s0); s0 = fmaf(f0.y, b0.y, s0);            \
            s1 = fmaf(f1.x, b0.z, s1); s1 = fmaf(f1.y, b0.w, s1);            \
            s2 = fmaf(f2.x, b1.x, s2); s2 = fmaf(f2.y, b1.y, s2);            \
            s3 = fmaf(f3.x, b1.z, s3); s3 = fmaf(f3.y, b1.w, s3);            \
        }                                                                    \
        float s = (s0 + s1) + (s2 + s3);                                     \
        _Pragma("unroll")                                                    \
        for (int o = 16; o; o >>= 1) s += __shfl_xor_sync(0xffffffffu, s, o);\
        if (lane == 0) sm[JJ][w] = s;                                        \
    }

    CELL_PREFETCH(bufB, 1);
    CELL_COMPUTE(bufA, 0);
    CELL_PREFETCH(bufA, 2);
    CELL_COMPUTE(bufB, 1);
    CELL_PREFETCH(bufB, 3);
    CELL_COMPUTE(bufA, 2);
    CELL_COMPUTE(bufB, 3);
#undef CELL_PREFETCH
#undef CELL_COMPUTE

    __syncthreads();

    if (tid < JPB) {
        const int j = j0 + tid;
        float gi = sm[tid][0] + sm[tid][4] + bih[j]         + bhh[j];
        float gf = sm[tid][1] + sm[tid][5] + bih[H + j]     + bhh[H + j];
        float gg = sm[tid][2] + sm[tid][6] + bih[2 * H + j] + bhh[2 * H + j];
        float go = sm[tid][3] + sm[tid][7] + bih[3 * H + j] + bhh[3 * H + j];
        float i_ = 1.0f / (1.0f + expf(-gi));
        float f_ = 1.0f / (1.0f + expf(-gf));
        float g_ = tanhf(gg);
        float o_ = 1.0f / (1.0f + expf(-go));
        float cn = f_ * g_c[layer][j] + i_ * g_;
        g_c[layer][j] = cn;
        g_h[par_out][layer][j] = o_ * tanhf(cn);
    }
}

// ---------------- fused head + sample ----------------
__global__ void __launch_bounds__(256)
head_sample_kernel(const float* __restrict__ hw, const float* __restrict__ hb,
                   const float* __restrict__ action_emb,
                   int t, float* __restrict__ out, int out_size) {
    const int r    = blockIdx.x & (NACT - 1);
    const int half = blockIdx.x >> 6;
    const int tid  = threadIdx.x;
    const int par_out = (t + 1) & 1;

    {
        const float4* row = reinterpret_cast<const float4*>(hw + (size_t)r * H);
        const float4* v4  = reinterpret_cast<const float4*>(g_h[par_out][1]);
        int k = half * 256 + tid;
        float4 a = row[k];
        float4 b = v4[k];
        float s = a.x * b.x + a.y * b.y + a.z * b.z + a.w * b.w;
#pragma unroll
        for (int o = 16; o; o >>= 1) s += __shfl_xor_sync(0xffffffffu, s, o);
        __shared__ float sm[8];
        if ((tid & 31) == 0) sm[tid >> 5] = s;
        __syncthreads();
        if (tid == 0) {
            g_part[half][r] = sm[0] + sm[1] + sm[2] + sm[3]
                            + sm[4] + sm[5] + sm[6] + sm[7];
        }
    }

    __shared__ int s_last;
    if (tid == 0) {
        __threadfence();
        int old = atomicAdd(&g_done, 1);
        s_last = (old == 2 * NACT - 1) ? 1 : 0;
        if (s_last) g_done = 0;
    }
    __syncthreads();
    if (!s_last) return;
    __threadfence();

    __shared__ float sl[NACT];
    if (tid < 32) {
        const int lane = tid;
        float l0 = g_part[0][lane]      + g_part[1][lane]      + hb[lane];
        float l1 = g_part[0][lane + 32] + g_part[1][lane + 32] + hb[lane + 32];
        sl[lane] = l0;
        sl[lane + 32] = l1;

        uint32_t kk0, kk1;
        threefry2x32(0u, 42u, 0u, (uint32_t)t, kk0, kk1);
        uint32_t a0, a1, b0, b1;
        threefry2x32(kk0, kk1, 0u, (uint32_t)lane,        a0, a1);
        threefry2x32(kk0, kk1, 0u, (uint32_t)(lane + 32), b0, b1);
        float u0 = jax_uniform(a0 ^ a1);
        float u1 = jax_uniform(b0 ^ b1);
        float gum0 = -logf(-logf(u0));
        float gum1 = -logf(-logf(u1));

        float v0 = l0 + gum0;
        float v1 = l1 + gum1;

        float bestv; int besti;
        if (v1 > v0) { bestv = v1; besti = lane + 32; }
        else         { bestv = v0; besti = lane; }
#pragma unroll
        for (int o = 16; o; o >>= 1) {
            float ov = __shfl_xor_sync(0xffffffffu, bestv, o);
            int   oi = __shfl_xor_sync(0xffffffffu, besti, o);
            if (ov > bestv || (ov == bestv && oi < besti)) { bestv = ov; besti = oi; }
        }
        float m = fmaxf(l0, l1);
#pragma unroll
        for (int o = 16; o; o >>= 1) m = fmaxf(m, __shfl_xor_sync(0xffffffffu, m, o));
        float se = expf(l0 - m) + expf(l1 - m);
#pragma unroll
        for (int o = 16; o; o >>= 1) se += __shfl_xor_sync(0xffffffffu, se, o);

        if (lane == 0) {
            float logp = (sl[besti] - m) - logf(se);
            float news = g_logp_sum + logp;
            g_logp_sum = news;
            g_action   = besti;
            out[t] = (float)besti;
            if (t == STEPS - 1 && out_size > STEPS) out[STEPS] = news;
        }
    }
    __syncthreads();
    int a = g_action;
    const float* src = action_emb + (size_t)a * H;
    for (int k = tid; k < H; k += 256) g_x[k] = src[k];
}

// ---------------- launch ----------------
extern "C" void kernel_launch(void* const* d_in, const int* in_sizes, int n_in,
                              void* d_out, int out_size) {
    const float* start_token = (const float*)d_in[0];
    const float* action_emb  = (const float*)d_in[1];
    const float* w_ih        = (const float*)d_in[2];
    const float* w_hh        = (const float*)d_in[3];
    const float* b_ih        = (const float*)d_in[4];
    const float* b_hh        = (const float*)d_in[5];
    const float* head_w      = (const float*)d_in[6];
    const float* head_b      = (const float*)d_in[7];
    float* out = (float*)d_out;

    convert_kernel<<<4096, 256>>>(w_ih, w_hh);
    init_kernel<<<(H + 255) / 256, 256>>>(start_token);

    for (int t = 0; t < STEPS; t++) {
        for (int l = 0; l < NLAYERS; l++) {
            cell_kernel<<<H / JPB, 256>>>(b_ih + (size_t)l * 4 * H,
                                          b_hh + (size_t)l * 4 * H,
                                          l, t);
        }
        head_sample_kernel<<<2 * NACT, 256>>>(head_w + (size_t)t * NACT * H,
                                              head_b + (size_t)t * NACT,
                                              action_emb, t, out, out_size);
    }
}